// round 1
// baseline (speedup 1.0000x reference)
#include <cuda_runtime.h>
#include <math.h>

#define Bb   4
#define Ss   512
#define Dd   512
#define Hh   2048
#define Ee   8
#define KK   2
#define NTOK (Bb*Ss)      // 2048 tokens
#define NPAIR (NTOK*KK)   // 4096 (token, k) pairs

#define BM 128
#define BN 128
#define BK 8

// ---------------- device scratch (no allocations allowed) ----------------
__device__ float g_ln_ctx[NTOK*Dd];   // LN(context)
__device__ float g_base[NTOK*Dd];     // LN(x) + q*qual_W + qual_b + ctx_b
__device__ float g_rf[NTOK*Dd];       // router features
__device__ float g_h[NPAIR*Hh];       // gelu(x@W1+b1) per selected pair
__device__ float g_y[NPAIR*Dd];       // gate*(h@W2+b2) per selected pair
__device__ int   g_elist[Ee*NTOK];    // pair ids bucketed by expert
__device__ int   g_ecount[Ee];
__device__ float g_gate[NPAIR];
__device__ float g_aux[Ee+2];         // [0..7]=sum probs, [8]=sum lse^2, [9]=sum entropy

// ---------------- init: zero per-launch accumulators ----------------
__global__ void k_init() {
    int i = threadIdx.x;
    if (i < Ee) g_ecount[i] = 0;
    if (i < Ee+2) g_aux[i] = 0.f;
}

// ---------------- LayerNorms (warp per token) ----------------
__global__ void k_ln(const float* __restrict__ x, const float* __restrict__ ctx,
                     const float* __restrict__ quality,
                     const float* __restrict__ rn_g, const float* __restrict__ rn_b,
                     const float* __restrict__ cn_g, const float* __restrict__ cn_b,
                     const float* __restrict__ ctx_b,
                     const float* __restrict__ qual_W, const float* __restrict__ qual_b)
{
    int warp = threadIdx.x >> 5, lane = threadIdx.x & 31;
    int t = blockIdx.x * 8 + warp;
    const float* xr = x + (size_t)t * Dd;
    const float* cr = ctx + (size_t)t * Dd;
    float xv[16], cv[16];
    float xs = 0.f, xs2 = 0.f, cs = 0.f, cs2 = 0.f;
#pragma unroll
    for (int i = 0; i < 16; i++) {
        float a = xr[i*32 + lane];
        float c = cr[i*32 + lane];
        xv[i] = a; cv[i] = c;
        xs += a; xs2 += a*a;
        cs += c; cs2 += c*c;
    }
#pragma unroll
    for (int o = 16; o > 0; o >>= 1) {
        xs  += __shfl_xor_sync(~0u, xs,  o);
        xs2 += __shfl_xor_sync(~0u, xs2, o);
        cs  += __shfl_xor_sync(~0u, cs,  o);
        cs2 += __shfl_xor_sync(~0u, cs2, o);
    }
    const float invD = 1.f / (float)Dd;
    float mx = xs * invD, vx = xs2 * invD - mx*mx;
    float mc = cs * invD, vc = cs2 * invD - mc*mc;
    float rx = rsqrtf(vx + 1e-5f);
    float rc = rsqrtf(vc + 1e-5f);
    float q = quality[t / Ss];
#pragma unroll
    for (int i = 0; i < 16; i++) {
        int d = i*32 + lane;
        g_ln_ctx[(size_t)t*Dd + d] = (cv[i] - mc) * rc * cn_g[d] + cn_b[d];
        g_base[(size_t)t*Dd + d]   = (xv[i] - mx) * rx * rn_g[d] + rn_b[d]
                                     + q * qual_W[d] + qual_b[d] + ctx_b[d];
    }
}

// ---------------- common 128x128x8 tile compute ----------------
#define GEMM_COMPUTE()                                                        \
    do {                                                                      \
        _Pragma("unroll")                                                     \
        for (int k = 0; k < BK; k++) {                                        \
            float4 a0 = *(const float4*)&As[k][ty*8];                         \
            float4 a1 = *(const float4*)&As[k][ty*8+4];                       \
            float4 b0 = *(const float4*)&Bs[k][tx*8];                         \
            float4 b1 = *(const float4*)&Bs[k][tx*8+4];                       \
            float a[8] = {a0.x,a0.y,a0.z,a0.w,a1.x,a1.y,a1.z,a1.w};           \
            float b[8] = {b0.x,b0.y,b0.z,b0.w,b1.x,b1.y,b1.z,b1.w};           \
            _Pragma("unroll")                                                 \
            for (int i = 0; i < 8; i++)                                       \
                _Pragma("unroll")                                             \
                for (int j = 0; j < 8; j++)                                   \
                    acc[i][j] += a[i] * b[j];                                 \
        }                                                                     \
    } while (0)

// ---------------- GEMM0: rf = ln_ctx @ ctx_W + base ----------------
__global__ __launch_bounds__(256)
void k_gemm0(const float* __restrict__ ctxW)
{
    __shared__ float As[BK][BM];
    __shared__ float Bs[BK][BN];
    int tid = threadIdx.x;
    int tx = tid & 15, ty = tid >> 4;
    int m0 = blockIdx.y * BM, n0 = blockIdx.x * BN;
    float acc[8][8] = {};
    int arow = tid >> 1, akq = tid & 1;
    int brow = tid >> 5, bcol = (tid & 31) * 4;
    const float* Aptr = g_ln_ctx + (size_t)(m0 + arow) * Dd + akq*4;
    const float* Bptr = ctxW + n0 + bcol;
    for (int k0 = 0; k0 < Dd; k0 += BK) {
        float4 av = *(const float4*)(Aptr + k0);
        As[akq*4+0][arow] = av.x; As[akq*4+1][arow] = av.y;
        As[akq*4+2][arow] = av.z; As[akq*4+3][arow] = av.w;
        float4 bv = *(const float4*)(Bptr + (size_t)(k0 + brow) * Dd);
        *(float4*)&Bs[brow][bcol] = bv;
        __syncthreads();
        GEMM_COMPUTE();
        __syncthreads();
    }
#pragma unroll
    for (int i = 0; i < 8; i++) {
        size_t row = (size_t)(m0 + ty*8 + i) * Dd;
#pragma unroll
        for (int j = 0; j < 8; j++) {
            int col = n0 + tx*8 + j;
            g_rf[row + col] = acc[i][j] + g_base[row + col];
        }
    }
}

// ---------------- Router: logits, top-2, gates, aux stats, bucketing ----------------
__global__ void k_router(const float* __restrict__ rtrW, const float* __restrict__ rtrb,
                         const float* __restrict__ temp)
{
    int warp = threadIdx.x >> 5, lane = threadIdx.x & 31;
    int t = blockIdx.x * 8 + warp;
    const float* rf = g_rf + (size_t)t * Dd;
    float lg[8] = {};
#pragma unroll
    for (int i = 0; i < 16; i++) {
        int d = i*32 + lane;
        float v = rf[d];
        const float4* w = (const float4*)(rtrW + (size_t)d * Ee);
        float4 w0 = w[0], w1 = w[1];
        lg[0] += v*w0.x; lg[1] += v*w0.y; lg[2] += v*w0.z; lg[3] += v*w0.w;
        lg[4] += v*w1.x; lg[5] += v*w1.y; lg[6] += v*w1.z; lg[7] += v*w1.w;
    }
#pragma unroll
    for (int o = 16; o > 0; o >>= 1)
#pragma unroll
        for (int e = 0; e < 8; e++)
            lg[e] += __shfl_xor_sync(~0u, lg[e], o);
    if (lane == 0) {
        float invT = 1.f / fmaxf(temp[0], 0.25f);
        float l[8];
#pragma unroll
        for (int e = 0; e < 8; e++) l[e] = (lg[e] + rtrb[e]) * invT;
        float mx = l[0];
#pragma unroll
        for (int e = 1; e < 8; e++) mx = fmaxf(mx, l[e]);
        float ex[8], se = 0.f;
#pragma unroll
        for (int e = 0; e < 8; e++) { ex[e] = expf(l[e] - mx); se += ex[e]; }
        float lse = logf(se) + mx;
        float inv_se = 1.f / se;
        float ent = 0.f;
#pragma unroll
        for (int e = 0; e < 8; e++) {
            float p = ex[e] * inv_se;
            ent -= p * logf(fmaxf(p, 1e-9f));
            atomicAdd(&g_aux[e], p);
        }
        atomicAdd(&g_aux[8], lse * lse);
        atomicAdd(&g_aux[9], ent);
        // top-2, ties -> lower index (matches jax.lax.top_k)
        int i0 = 0;
#pragma unroll
        for (int e = 1; e < 8; e++) if (l[e] > l[i0]) i0 = e;
        int i1 = (i0 == 0) ? 1 : 0;
#pragma unroll
        for (int e = 0; e < 8; e++) { if (e == i0 || e == i1) continue; if (l[e] > l[i1]) i1 = e; }
        float d1 = expf(l[i1] - l[i0]);
        float g0 = 1.f / (1.f + d1);
        float g1 = d1 * g0;
        int p0 = t*2, p1 = t*2 + 1;
        g_gate[p0] = g0; g_gate[p1] = g1;
        int s0 = atomicAdd(&g_ecount[i0], 1);
        g_elist[i0*NTOK + s0] = p0;
        int s1 = atomicAdd(&g_ecount[i1], 1);
        g_elist[i1*NTOK + s1] = p1;
    }
}

// ---------------- GEMM1 (grouped, gathered rows): h = gelu(x[tok] @ W1[e] + b1[e]) ----------------
__global__ __launch_bounds__(256)
void k_gemm1(const float* __restrict__ x, const float* __restrict__ W1,
             const float* __restrict__ b1)
{
    __shared__ float As[BK][BM];
    __shared__ float Bs[BK][BN];
    __shared__ int sPair[BM];
    __shared__ int sTokOff[BM];
    int e = blockIdx.z;
    int cnt = g_ecount[e];
    int m0 = blockIdx.y * BM;
    if (m0 >= cnt) return;
    int n0 = blockIdx.x * BN;
    int tid = threadIdx.x;
    if (tid < BM) {
        int gm = m0 + tid;
        int p = g_elist[e*NTOK + (gm < cnt ? gm : 0)];
        sPair[tid] = p;
        sTokOff[tid] = (p >> 1) * Dd;
    }
    __syncthreads();
    int tx = tid & 15, ty = tid >> 4;
    float acc[8][8] = {};
    int arow = tid >> 1, akq = tid & 1;
    int brow = tid >> 5, bcol = (tid & 31) * 4;
    int aoff = sTokOff[arow] + akq*4;
    const float* Bbase = W1 + (size_t)e * Dd * Hh + n0 + bcol;
    for (int k0 = 0; k0 < Dd; k0 += BK) {
        float4 av = *(const float4*)(x + aoff + k0);
        As[akq*4+0][arow] = av.x; As[akq*4+1][arow] = av.y;
        As[akq*4+2][arow] = av.z; As[akq*4+3][arow] = av.w;
        float4 bv = *(const float4*)(Bbase + (size_t)(k0 + brow) * Hh);
        *(float4*)&Bs[brow][bcol] = bv;
        __syncthreads();
        GEMM_COMPUTE();
        __syncthreads();
    }
#pragma unroll
    for (int i = 0; i < 8; i++) {
        int m = ty*8 + i;
        if (m0 + m < cnt) {
            int p = sPair[m];
            float* orow = g_h + (size_t)p * Hh + n0;
            const float* brow2 = b1 + (size_t)e * Hh + n0;
#pragma unroll
            for (int j = 0; j < 8; j++) {
                int n = tx*8 + j;
                float v = acc[i][j] + brow2[n];
                orow[n] = 0.5f * v * (1.f + erff(v * 0.70710678118f));
            }
        }
    }
}

// ---------------- GEMM2 (grouped): y = gate * (h @ W2[e] + b2[e]) ----------------
__global__ __launch_bounds__(256)
void k_gemm2(const float* __restrict__ W2, const float* __restrict__ b2)
{
    __shared__ float As[BK][BM];
    __shared__ float Bs[BK][BN];
    __shared__ int sPair[BM];
    int e = blockIdx.z;
    int cnt = g_ecount[e];
    int m0 = blockIdx.y * BM;
    if (m0 >= cnt) return;
    int n0 = blockIdx.x * BN;
    int tid = threadIdx.x;
    if (tid < BM) {
        int gm = m0 + tid;
        sPair[tid] = g_elist[e*NTOK + (gm < cnt ? gm : 0)];
    }
    __syncthreads();
    int tx = tid & 15, ty = tid >> 4;
    float acc[8][8] = {};
    int arow = tid >> 1, akq = tid & 1;
    int brow = tid >> 5, bcol = (tid & 31) * 4;
    size_t aoff = (size_t)sPair[arow] * Hh + akq*4;
    const float* Bbase = W2 + (size_t)e * Hh * Dd + n0 + bcol;
    for (int k0 = 0; k0 < Hh; k0 += BK) {
        float4 av = *(const float4*)(g_h + aoff + k0);
        As[akq*4+0][arow] = av.x; As[akq*4+1][arow] = av.y;
        As[akq*4+2][arow] = av.z; As[akq*4+3][arow] = av.w;
        float4 bv = *(const float4*)(Bbase + (size_t)(k0 + brow) * Dd);
        *(float4*)&Bs[brow][bcol] = bv;
        __syncthreads();
        GEMM_COMPUTE();
        __syncthreads();
    }
#pragma unroll
    for (int i = 0; i < 8; i++) {
        int m = ty*8 + i;
        if (m0 + m < cnt) {
            int p = sPair[m];
            float gate = g_gate[p];
            float* orow = g_y + (size_t)p * Dd + n0;
            const float* brow2 = b2 + (size_t)e * Dd + n0;
#pragma unroll
            for (int j = 0; j < 8; j++) {
                int n = tx*8 + j;
                orow[n] = gate * (acc[i][j] + brow2[n]);
            }
        }
    }
}

// ---------------- combine: out[t,:] = y[2t,:] + y[2t+1,:] ----------------
__global__ void k_combine(float* __restrict__ out)
{
    int i = blockIdx.x * 256 + threadIdx.x;   // i in [0, NTOK*Dd)
    int t = i >> 9;                            // Dd = 512
    int d = i & 511;
    size_t base = (size_t)t * (2*Dd) + d;
    out[i] = g_y[base] + g_y[base + Dd];
}

// ---------------- finalize aux scalars ----------------
__global__ void k_finalize(float* __restrict__ out)
{
    if (threadIdx.x == 0) {
        const float inv = 1.f / (float)NTOK;
        float lb = 0.f;
#pragma unroll
        for (int e = 0; e < Ee; e++) {
            float d = g_aux[e] * inv - 1.f / (float)Ee;
            lb += d * d;
        }
        lb *= 1.f / (float)Ee;
        float rz = g_aux[8] * inv;
        float ent = g_aux[9] * inv;
        out[NTOK*Dd + 0] = lb;
        out[NTOK*Dd + 1] = rz;
        out[NTOK*Dd + 2] = ent;
        out[NTOK*Dd + 3] = lb + 0.001f * rz - 0.001f * ent;
    }
}

// ---------------- launch ----------------
extern "C" void kernel_launch(void* const* d_in, const int* in_sizes, int n_in,
                              void* d_out, int out_size)
{
    const float* x       = (const float*)d_in[0];
    const float* ctx     = (const float*)d_in[1];
    const float* quality = (const float*)d_in[2];
    const float* rn_g    = (const float*)d_in[3];
    const float* rn_b    = (const float*)d_in[4];
    const float* cn_g    = (const float*)d_in[5];
    const float* cn_b    = (const float*)d_in[6];
    const float* ctx_W   = (const float*)d_in[7];
    const float* ctx_b   = (const float*)d_in[8];
    const float* qual_W  = (const float*)d_in[9];
    const float* qual_b  = (const float*)d_in[10];
    const float* rtr_W   = (const float*)d_in[11];
    const float* rtr_b   = (const float*)d_in[12];
    const float* temp    = (const float*)d_in[13];
    const float* W1      = (const float*)d_in[14];
    const float* b1      = (const float*)d_in[15];
    const float* W2      = (const float*)d_in[16];
    const float* b2      = (const float*)d_in[17];
    float* out = (float*)d_out;

    k_init<<<1, 32>>>();
    k_ln<<<NTOK/8, 256>>>(x, ctx, quality, rn_g, rn_b, cn_g, cn_b, ctx_b, qual_W, qual_b);
    k_gemm0<<<dim3(Dd/BN, NTOK/BM), 256>>>(ctx_W);
    k_router<<<NTOK/8, 256>>>(rtr_W, rtr_b, temp);
    k_gemm1<<<dim3(Hh/BN, NTOK/BM, Ee), 256>>>(x, W1, b1);
    k_gemm2<<<dim3(Dd/BN, NTOK/BM, Ee), 256>>>(W2, b2);
    k_combine<<<(NTOK*Dd)/256, 256>>>(out);
    k_finalize<<<1, 32>>>(out);
}

// round 2
// speedup vs baseline: 1.2425x; 1.2425x over previous
#include <cuda_runtime.h>
#include <math.h>
#include <stdint.h>

#define Bb   4
#define Ss   512
#define Dd   512
#define Hh   2048
#define Ee   8
#define KK   2
#define NTOK (Bb*Ss)      // 2048 tokens
#define NPAIR (NTOK*KK)   // 4096 (token, k) pairs

#define BM 128
#define BN 128
#define BK 16
#define LDS_PAD 136       // 128+8: stride ≡ 8 (mod 32) -> conflict-free frag loads

// ---------------- device scratch (no allocations allowed) ----------------
__device__ float g_ln_ctx[NTOK*Dd];   // LN(context)
__device__ float g_base[NTOK*Dd];     // LN(x) + q*qual_W + qual_b + ctx_b
__device__ float g_rf[NTOK*Dd];       // router features
__device__ float g_h[NPAIR*Hh];       // gelu(x@W1+b1) per selected pair
__device__ float g_y[NPAIR*Dd];       // gate*(h@W2+b2) per selected pair
__device__ int   g_elist[Ee*NTOK];    // pair ids bucketed by expert
__device__ int   g_ecount[Ee];
__device__ float g_gate[NPAIR];
__device__ float g_aux[Ee+2];         // [0..7]=sum probs, [8]=sum lse^2, [9]=sum entropy

// ---------------- init ----------------
__global__ void k_init() {
    int i = threadIdx.x;
    if (i < Ee) g_ecount[i] = 0;
    if (i < Ee+2) g_aux[i] = 0.f;
}

// ---------------- LayerNorms (warp per token) ----------------
__global__ void k_ln(const float* __restrict__ x, const float* __restrict__ ctx,
                     const float* __restrict__ quality,
                     const float* __restrict__ rn_g, const float* __restrict__ rn_b,
                     const float* __restrict__ cn_g, const float* __restrict__ cn_b,
                     const float* __restrict__ ctx_b,
                     const float* __restrict__ qual_W, const float* __restrict__ qual_b)
{
    int warp = threadIdx.x >> 5, lane = threadIdx.x & 31;
    int t = blockIdx.x * 8 + warp;
    const float* xr = x + (size_t)t * Dd;
    const float* cr = ctx + (size_t)t * Dd;
    float xv[16], cv[16];
    float xs = 0.f, xs2 = 0.f, cs = 0.f, cs2 = 0.f;
#pragma unroll
    for (int i = 0; i < 16; i++) {
        float a = xr[i*32 + lane];
        float c = cr[i*32 + lane];
        xv[i] = a; cv[i] = c;
        xs += a; xs2 += a*a;
        cs += c; cs2 += c*c;
    }
#pragma unroll
    for (int o = 16; o > 0; o >>= 1) {
        xs  += __shfl_xor_sync(~0u, xs,  o);
        xs2 += __shfl_xor_sync(~0u, xs2, o);
        cs  += __shfl_xor_sync(~0u, cs,  o);
        cs2 += __shfl_xor_sync(~0u, cs2, o);
    }
    const float invD = 1.f / (float)Dd;
    float mx = xs * invD, vx = xs2 * invD - mx*mx;
    float mc = cs * invD, vc = cs2 * invD - mc*mc;
    float rx = rsqrtf(vx + 1e-5f);
    float rc = rsqrtf(vc + 1e-5f);
    float q = quality[t / Ss];
#pragma unroll
    for (int i = 0; i < 16; i++) {
        int d = i*32 + lane;
        g_ln_ctx[(size_t)t*Dd + d] = (cv[i] - mc) * rc * cn_g[d] + cn_b[d];
        g_base[(size_t)t*Dd + d]   = (xv[i] - mx) * rx * rn_g[d] + rn_b[d]
                                     + q * qual_W[d] + qual_b[d] + ctx_b[d];
    }
}

// ---------------- tf32 helpers ----------------
__device__ __forceinline__ void tf32_split(float x, uint32_t& hi, uint32_t& lo) {
    uint32_t h;
    asm("cvt.rna.tf32.f32 %0, %1;" : "=r"(h) : "f"(x));
    float hf = __uint_as_float(h);
    float l = x - hf;
    uint32_t lb;
    asm("cvt.rna.tf32.f32 %0, %1;" : "=r"(lb) : "f"(l));
    hi = h; lo = lb;
}

__device__ __forceinline__ void mma_tf32(float c[4],
                                         uint32_t a0, uint32_t a1, uint32_t a2, uint32_t a3,
                                         uint32_t b0, uint32_t b1) {
    asm volatile(
        "mma.sync.aligned.m16n8k8.row.col.f32.tf32.tf32.f32 "
        "{%0,%1,%2,%3}, {%4,%5,%6,%7}, {%8,%9}, {%0,%1,%2,%3};"
        : "+f"(c[0]), "+f"(c[1]), "+f"(c[2]), "+f"(c[3])
        : "r"(a0), "r"(a1), "r"(a2), "r"(a3), "r"(b0), "r"(b1));
}

// Per-iteration tile compute: 128x128 CTA tile, 8 warps as 4(M) x 2(N),
// each warp: 32(M) x 64(N) via m16n8k8 atoms, hi/lo split (3 MMAs per atom pair).
#define TILE_COMPUTE()                                                         \
    do {                                                                       \
        _Pragma("unroll")                                                      \
        for (int ks = 0; ks < 2; ks++) {                                       \
            int krow = ks*8 + (lane & 3);                                      \
            int mrow = warpM*32 + (lane >> 2);                                 \
            uint32_t ah[2][4], al[2][4];                                       \
            _Pragma("unroll")                                                  \
            for (int am = 0; am < 2; am++) {                                   \
                int r = mrow + am*16;                                          \
                ah[am][0] = sAhi[krow][r];   ah[am][1] = sAhi[krow][r+8];      \
                ah[am][2] = sAhi[krow+4][r]; ah[am][3] = sAhi[krow+4][r+8];    \
                al[am][0] = sAlo[krow][r];   al[am][1] = sAlo[krow][r+8];      \
                al[am][2] = sAlo[krow+4][r]; al[am][3] = sAlo[krow+4][r+8];    \
            }                                                                  \
            _Pragma("unroll")                                                  \
            for (int bn = 0; bn < 8; bn++) {                                   \
                int cc = warpN*64 + bn*8 + (lane >> 2);                        \
                uint32_t bh0 = sBhi[krow][cc], bh1 = sBhi[krow+4][cc];         \
                uint32_t bl0 = sBlo[krow][cc], bl1 = sBlo[krow+4][cc];         \
                _Pragma("unroll")                                              \
                for (int am = 0; am < 2; am++) {                               \
                    mma_tf32(acc[am][bn], ah[am][0],ah[am][1],ah[am][2],ah[am][3], bh0, bh1); \
                    mma_tf32(acc[am][bn], ah[am][0],ah[am][1],ah[am][2],ah[am][3], bl0, bl1); \
                    mma_tf32(acc[am][bn], al[am][0],al[am][1],al[am][2],al[am][3], bh0, bh1); \
                }                                                              \
            }                                                                  \
        }                                                                      \
    } while (0)

// A loader: thread tid loads 8 consecutive k-floats of one row, splits, stores transposed.
#define LOAD_A_TILE(srcptr)                                                    \
    do {                                                                       \
        const float4* p = (const float4*)(srcptr);                             \
        float4 v0 = p[0], v1 = p[1];                                           \
        float vv[8] = {v0.x,v0.y,v0.z,v0.w,v1.x,v1.y,v1.z,v1.w};               \
        _Pragma("unroll")                                                      \
        for (int j = 0; j < 8; j++) {                                          \
            uint32_t hi, lo; tf32_split(vv[j], hi, lo);                        \
            sAhi[akq*8+j][arow] = hi; sAlo[akq*8+j][arow] = lo;                \
        }                                                                      \
    } while (0)

// B loader: thread tid loads 8 consecutive n-floats of one k-row.
#define LOAD_B_TILE(srcptr)                                                    \
    do {                                                                       \
        const float4* p = (const float4*)(srcptr);                             \
        float4 v0 = p[0], v1 = p[1];                                           \
        float vv[8] = {v0.x,v0.y,v0.z,v0.w,v1.x,v1.y,v1.z,v1.w};               \
        _Pragma("unroll")                                                      \
        for (int j = 0; j < 8; j++) {                                          \
            uint32_t hi, lo; tf32_split(vv[j], hi, lo);                        \
            sBhi[bkrow][bnc+j] = hi; sBlo[bkrow][bnc+j] = lo;                  \
        }                                                                      \
    } while (0)

#define GEMM_PREAMBLE()                                                        \
    __shared__ uint32_t sAhi[BK][LDS_PAD];                                     \
    __shared__ uint32_t sAlo[BK][LDS_PAD];                                     \
    __shared__ uint32_t sBhi[BK][LDS_PAD];                                     \
    __shared__ uint32_t sBlo[BK][LDS_PAD];                                     \
    int tid = threadIdx.x;                                                     \
    int lane = tid & 31, wid = tid >> 5;                                       \
    int warpM = wid >> 1, warpN = wid & 1;                                     \
    int arow = tid >> 1, akq = tid & 1;                                        \
    int bkrow = tid >> 4, bnc = (tid & 15) * 8;                                \
    float acc[2][8][4];                                                        \
    _Pragma("unroll")                                                          \
    for (int i = 0; i < 2; i++)                                                \
        _Pragma("unroll")                                                      \
        for (int j = 0; j < 8; j++)                                            \
            _Pragma("unroll")                                                  \
            for (int q = 0; q < 4; q++) acc[i][j][q] = 0.f;

// ---------------- GEMM0: rf = ln_ctx @ ctx_W + base ----------------
__global__ __launch_bounds__(256)
void k_gemm0(const float* __restrict__ ctxW)
{
    GEMM_PREAMBLE();
    int m0 = blockIdx.y * BM, n0 = blockIdx.x * BN;
    const float* Aptr = g_ln_ctx + (size_t)(m0 + arow) * Dd + akq*8;
    const float* Bptr = ctxW + n0 + bnc;
    for (int k0 = 0; k0 < Dd; k0 += BK) {
        LOAD_A_TILE(Aptr + k0);
        LOAD_B_TILE(Bptr + (size_t)(k0 + bkrow) * Dd);
        __syncthreads();
        TILE_COMPUTE();
        __syncthreads();
    }
#pragma unroll
    for (int am = 0; am < 2; am++) {
#pragma unroll
        for (int bn = 0; bn < 8; bn++) {
            int col = n0 + warpN*64 + bn*8 + (lane & 3)*2;
            int r0 = m0 + warpM*32 + am*16 + (lane >> 2);
            size_t o0 = (size_t)r0 * Dd + col;
            size_t o1 = (size_t)(r0 + 8) * Dd + col;
            g_rf[o0]   = acc[am][bn][0] + g_base[o0];
            g_rf[o0+1] = acc[am][bn][1] + g_base[o0+1];
            g_rf[o1]   = acc[am][bn][2] + g_base[o1];
            g_rf[o1+1] = acc[am][bn][3] + g_base[o1+1];
        }
    }
}

// ---------------- Router ----------------
__global__ void k_router(const float* __restrict__ rtrW, const float* __restrict__ rtrb,
                         const float* __restrict__ temp)
{
    __shared__ float sprob[8][8];
    __shared__ float slse2[8];
    __shared__ float sent[8];
    int warp = threadIdx.x >> 5, lane = threadIdx.x & 31;
    int t = blockIdx.x * 8 + warp;
    const float* rf = g_rf + (size_t)t * Dd;
    float lg[8] = {};
#pragma unroll
    for (int i = 0; i < 16; i++) {
        int d = i*32 + lane;
        float v = rf[d];
        const float4* w = (const float4*)(rtrW + (size_t)d * Ee);
        float4 w0 = w[0], w1 = w[1];
        lg[0] += v*w0.x; lg[1] += v*w0.y; lg[2] += v*w0.z; lg[3] += v*w0.w;
        lg[4] += v*w1.x; lg[5] += v*w1.y; lg[6] += v*w1.z; lg[7] += v*w1.w;
    }
#pragma unroll
    for (int o = 16; o > 0; o >>= 1)
#pragma unroll
        for (int e = 0; e < 8; e++)
            lg[e] += __shfl_xor_sync(~0u, lg[e], o);
    if (lane == 0) {
        float invT = 1.f / fmaxf(temp[0], 0.25f);
        float l[8];
#pragma unroll
        for (int e = 0; e < 8; e++) l[e] = (lg[e] + rtrb[e]) * invT;
        float mx = l[0];
#pragma unroll
        for (int e = 1; e < 8; e++) mx = fmaxf(mx, l[e]);
        float ex[8], se = 0.f;
#pragma unroll
        for (int e = 0; e < 8; e++) { ex[e] = expf(l[e] - mx); se += ex[e]; }
        float lse = logf(se) + mx;
        float inv_se = 1.f / se;
        float ent = 0.f;
#pragma unroll
        for (int e = 0; e < 8; e++) {
            float p = ex[e] * inv_se;
            ent -= p * logf(fmaxf(p, 1e-9f));
            sprob[warp][e] = p;
        }
        slse2[warp] = lse * lse;
        sent[warp] = ent;
        // top-2, ties -> lower index (matches jax.lax.top_k)
        int i0 = 0;
#pragma unroll
        for (int e = 1; e < 8; e++) if (l[e] > l[i0]) i0 = e;
        int i1 = (i0 == 0) ? 1 : 0;
#pragma unroll
        for (int e = 0; e < 8; e++) { if (e == i0 || e == i1) continue; if (l[e] > l[i1]) i1 = e; }
        float d1 = expf(l[i1] - l[i0]);
        float g0 = 1.f / (1.f + d1);
        float g1 = d1 * g0;
        int p0 = t*2, p1 = t*2 + 1;
        g_gate[p0] = g0; g_gate[p1] = g1;
        int s0 = atomicAdd(&g_ecount[i0], 1);
        g_elist[i0*NTOK + s0] = p0;
        int s1 = atomicAdd(&g_ecount[i1], 1);
        g_elist[i1*NTOK + s1] = p1;
    }
    __syncthreads();
    // one atomic per block per statistic
    int tid = threadIdx.x;
    if (tid < 8) {
        float s = 0.f;
#pragma unroll
        for (int w = 0; w < 8; w++) s += sprob[w][tid];
        atomicAdd(&g_aux[tid], s);
    } else if (tid == 8) {
        float s = 0.f;
#pragma unroll
        for (int w = 0; w < 8; w++) s += slse2[w];
        atomicAdd(&g_aux[8], s);
    } else if (tid == 9) {
        float s = 0.f;
#pragma unroll
        for (int w = 0; w < 8; w++) s += sent[w];
        atomicAdd(&g_aux[9], s);
    }
}

// ---------------- GEMM1 (grouped, gathered rows): h = gelu(x[tok] @ W1[e] + b1[e]) ----------------
__global__ __launch_bounds__(256)
void k_gemm1(const float* __restrict__ x, const float* __restrict__ W1,
             const float* __restrict__ b1)
{
    __shared__ int sPair[BM];
    __shared__ int sTokOff[BM];
    int e = blockIdx.z;
    int cnt = g_ecount[e];
    int m0 = blockIdx.y * BM;
    if (m0 >= cnt) return;
    int n0 = blockIdx.x * BN;
    GEMM_PREAMBLE();
    if (tid < BM) {
        int gm = m0 + tid;
        int p = g_elist[e*NTOK + (gm < cnt ? gm : 0)];
        sPair[tid] = p;
        sTokOff[tid] = (p >> 1) * Dd;
    }
    __syncthreads();
    int aoff = sTokOff[arow] + akq*8;
    const float* Bbase = W1 + (size_t)e * Dd * Hh + n0 + bnc;
    for (int k0 = 0; k0 < Dd; k0 += BK) {
        LOAD_A_TILE(x + aoff + k0);
        LOAD_B_TILE(Bbase + (size_t)(k0 + bkrow) * Hh);
        __syncthreads();
        TILE_COMPUTE();
        __syncthreads();
    }
#pragma unroll
    for (int am = 0; am < 2; am++) {
#pragma unroll
        for (int bn = 0; bn < 8; bn++) {
            int col = n0 + warpN*64 + bn*8 + (lane & 3)*2;
            int mr0 = warpM*32 + am*16 + (lane >> 2);
#pragma unroll
            for (int half = 0; half < 2; half++) {
                int m = mr0 + half*8;
                if (m0 + m < cnt) {
                    int p = sPair[m];
                    float* orow = g_h + (size_t)p * Hh;
                    const float* br = b1 + (size_t)e * Hh;
                    float v0 = acc[am][bn][half*2]   + br[col];
                    float v1 = acc[am][bn][half*2+1] + br[col+1];
                    orow[col]   = 0.5f * v0 * (1.f + erff(v0 * 0.70710678118f));
                    orow[col+1] = 0.5f * v1 * (1.f + erff(v1 * 0.70710678118f));
                }
            }
        }
    }
}

// ---------------- GEMM2 (grouped): y = gate * (h @ W2[e] + b2[e]) ----------------
__global__ __launch_bounds__(256)
void k_gemm2(const float* __restrict__ W2, const float* __restrict__ b2)
{
    __shared__ int sPair[BM];
    int e = blockIdx.z;
    int cnt = g_ecount[e];
    int m0 = blockIdx.y * BM;
    if (m0 >= cnt) return;
    int n0 = blockIdx.x * BN;
    GEMM_PREAMBLE();
    if (tid < BM) {
        int gm = m0 + tid;
        sPair[tid] = g_elist[e*NTOK + (gm < cnt ? gm : 0)];
    }
    __syncthreads();
    size_t aoff = (size_t)sPair[arow] * Hh + akq*8;
    const float* Bbase = W2 + (size_t)e * Hh * Dd + n0 + bnc;
    for (int k0 = 0; k0 < Hh; k0 += BK) {
        LOAD_A_TILE(g_h + aoff + k0);
        LOAD_B_TILE(Bbase + (size_t)(k0 + bkrow) * Dd);
        __syncthreads();
        TILE_COMPUTE();
        __syncthreads();
    }
#pragma unroll
    for (int am = 0; am < 2; am++) {
#pragma unroll
        for (int bn = 0; bn < 8; bn++) {
            int col = n0 + warpN*64 + bn*8 + (lane & 3)*2;
            int mr0 = warpM*32 + am*16 + (lane >> 2);
#pragma unroll
            for (int half = 0; half < 2; half++) {
                int m = mr0 + half*8;
                if (m0 + m < cnt) {
                    int p = sPair[m];
                    float gate = g_gate[p];
                    float* orow = g_y + (size_t)p * Dd;
                    const float* br = b2 + (size_t)e * Dd;
                    orow[col]   = gate * (acc[am][bn][half*2]   + br[col]);
                    orow[col+1] = gate * (acc[am][bn][half*2+1] + br[col+1]);
                }
            }
        }
    }
}

// ---------------- combine: out[t,:] = y[2t,:] + y[2t+1,:] ----------------
__global__ void k_combine(float* __restrict__ out)
{
    int i = blockIdx.x * 256 + threadIdx.x;
    int t = i >> 9;
    int d = i & 511;
    size_t base = (size_t)t * (2*Dd) + d;
    out[i] = g_y[base] + g_y[base + Dd];
}

// ---------------- finalize aux scalars ----------------
__global__ void k_finalize(float* __restrict__ out)
{
    if (threadIdx.x == 0) {
        const float inv = 1.f / (float)NTOK;
        float lb = 0.f;
#pragma unroll
        for (int e = 0; e < Ee; e++) {
            float d = g_aux[e] * inv - 1.f / (float)Ee;
            lb += d * d;
        }
        lb *= 1.f / (float)Ee;
        float rz = g_aux[8] * inv;
        float ent = g_aux[9] * inv;
        out[NTOK*Dd + 0] = lb;
        out[NTOK*Dd + 1] = rz;
        out[NTOK*Dd + 2] = ent;
        out[NTOK*Dd + 3] = lb + 0.001f * rz - 0.001f * ent;
    }
}

// ---------------- launch ----------------
extern "C" void kernel_launch(void* const* d_in, const int* in_sizes, int n_in,
                              void* d_out, int out_size)
{
    const float* x       = (const float*)d_in[0];
    const float* ctx     = (const float*)d_in[1];
    const float* quality = (const float*)d_in[2];
    const float* rn_g    = (const float*)d_in[3];
    const float* rn_b    = (const float*)d_in[4];
    const float* cn_g    = (const float*)d_in[5];
    const float* cn_b    = (const float*)d_in[6];
    const float* ctx_W   = (const float*)d_in[7];
    const float* ctx_b   = (const float*)d_in[8];
    const float* qual_W  = (const float*)d_in[9];
    const float* qual_b  = (const float*)d_in[10];
    const float* rtr_W   = (const float*)d_in[11];
    const float* rtr_b   = (const float*)d_in[12];
    const float* temp    = (const float*)d_in[13];
    const float* W1      = (const float*)d_in[14];
    const float* b1      = (const float*)d_in[15];
    const float* W2      = (const float*)d_in[16];
    const float* b2      = (const float*)d_in[17];
    float* out = (float*)d_out;

    k_init<<<1, 32>>>();
    k_ln<<<NTOK/8, 256>>>(x, ctx, quality, rn_g, rn_b, cn_g, cn_b, ctx_b, qual_W, qual_b);
    k_gemm0<<<dim3(Dd/BN, NTOK/BM), 256>>>(ctx_W);
    k_router<<<NTOK/8, 256>>>(rtr_W, rtr_b, temp);
    k_gemm1<<<dim3(Hh/BN, NTOK/BM, Ee), 256>>>(x, W1, b1);
    k_gemm2<<<dim3(Dd/BN, NTOK/BM, Ee), 256>>>(W2, b2);
    k_combine<<<(NTOK*Dd)/256, 256>>>(out);
    k_finalize<<<1, 32>>>(out);
}

// round 3
// speedup vs baseline: 2.8013x; 2.2545x over previous
#include <cuda_runtime.h>
#include <math.h>
#include <stdint.h>

#define Bb   4
#define Ss   512
#define Dd   512
#define Hh   2048
#define Ee   8
#define KK   2
#define NTOK (Bb*Ss)      // 2048 tokens
#define NPAIR (NTOK*KK)   // 4096 (token, k) pairs

#define BM 128
#define BN 128
#define BKK 32            // k per mainloop iter
#define KP  16            // k-pairs per iter (BKK/2)
#define PAD 136           // row pitch (words) for [kp][col] smem tiles

// ---------------- device scratch ----------------
__device__ float    g_ln_ctx[NTOK*Dd];
__device__ float    g_base[NTOK*Dd];
__device__ float    g_rf[NTOK*Dd];
__device__ uint32_t g_hhi[NPAIR*(Hh/2)];   // h packed bf16x2 (hi part), k-pairs on H
__device__ uint32_t g_hlo[NPAIR*(Hh/2)];   // h packed bf16x2 (lo part)
__device__ float    g_y[NPAIR*Dd];
__device__ int      g_elist[Ee*NTOK];
__device__ int      g_ecount[Ee];
__device__ float    g_gate[NPAIR];
__device__ float    g_aux[Ee+2];

// ---------------- init ----------------
__global__ void k_init() {
    int i = threadIdx.x;
    if (i < Ee) g_ecount[i] = 0;
    if (i < Ee+2) g_aux[i] = 0.f;
}

// ---------------- LayerNorms (warp per token) ----------------
__global__ void k_ln(const float* __restrict__ x, const float* __restrict__ ctx,
                     const float* __restrict__ quality,
                     const float* __restrict__ rn_g, const float* __restrict__ rn_b,
                     const float* __restrict__ cn_g, const float* __restrict__ cn_b,
                     const float* __restrict__ ctx_b,
                     const float* __restrict__ qual_W, const float* __restrict__ qual_b)
{
    int warp = threadIdx.x >> 5, lane = threadIdx.x & 31;
    int t = blockIdx.x * 8 + warp;
    const float* xr = x + (size_t)t * Dd;
    const float* cr = ctx + (size_t)t * Dd;
    float xv[16], cv[16];
    float xs = 0.f, xs2 = 0.f, cs = 0.f, cs2 = 0.f;
#pragma unroll
    for (int i = 0; i < 16; i++) {
        float a = xr[i*32 + lane];
        float c = cr[i*32 + lane];
        xv[i] = a; cv[i] = c;
        xs += a; xs2 += a*a;
        cs += c; cs2 += c*c;
    }
#pragma unroll
    for (int o = 16; o > 0; o >>= 1) {
        xs  += __shfl_xor_sync(~0u, xs,  o);
        xs2 += __shfl_xor_sync(~0u, xs2, o);
        cs  += __shfl_xor_sync(~0u, cs,  o);
        cs2 += __shfl_xor_sync(~0u, cs2, o);
    }
    const float invD = 1.f / (float)Dd;
    float mx = xs * invD, vx = xs2 * invD - mx*mx;
    float mc = cs * invD, vc = cs2 * invD - mc*mc;
    float rx = rsqrtf(vx + 1e-5f);
    float rc = rsqrtf(vc + 1e-5f);
    float q = quality[t / Ss];
#pragma unroll
    for (int i = 0; i < 16; i++) {
        int d = i*32 + lane;
        g_ln_ctx[(size_t)t*Dd + d] = (cv[i] - mc) * rc * cn_g[d] + cn_b[d];
        g_base[(size_t)t*Dd + d]   = (xv[i] - mx) * rx * rn_g[d] + rn_b[d]
                                     + q * qual_W[d] + qual_b[d] + ctx_b[d];
    }
}

// ---------------- bf16 split helpers ----------------
// x = hi + lo, hi = truncate-to-bf16(x), lo = rn-bf16(x - hi).
// Packs two consecutive-k values into one bf16x2 word (low half = first k).
__device__ __forceinline__ void split_pair(float x0, float x1, uint32_t& hi, uint32_t& lo) {
    uint32_t u0 = __float_as_uint(x0), u1 = __float_as_uint(x1);
    hi = __byte_perm(u0, u1, 0x7632);
    float r0 = x0 - __uint_as_float(u0 & 0xFFFF0000u);
    float r1 = x1 - __uint_as_float(u1 & 0xFFFF0000u);
    asm("cvt.rn.bf16x2.f32 %0, %1, %2;" : "=r"(lo) : "f"(r1), "f"(r0));
}

__device__ __forceinline__ void mma_bf16(float c[4],
                                         uint32_t a0, uint32_t a1, uint32_t a2, uint32_t a3,
                                         uint32_t b0, uint32_t b1) {
    asm volatile(
        "mma.sync.aligned.m16n8k16.row.col.f32.bf16.bf16.f32 "
        "{%0,%1,%2,%3}, {%4,%5,%6,%7}, {%8,%9}, {%0,%1,%2,%3};"
        : "+f"(c[0]), "+f"(c[1]), "+f"(c[2]), "+f"(c[3])
        : "r"(a0), "r"(a1), "r"(a2), "r"(a3), "r"(b0), "r"(b1));
}

// ---------------- shared tile struct ----------------
struct SmemT {
    uint32_t Ahi[KP][PAD];
    uint32_t Alo[KP][PAD];
    uint32_t Bhi[KP][PAD];
    uint32_t Blo[KP][PAD];
};

// per-iter compute: 128x128 CTA tile, 8 warps 4(M)x2(N), warp = 32M x 64N
__device__ __forceinline__ void tile_compute(SmemT& sm, float acc[2][8][4],
                                             int lane, int warpM, int warpN)
{
    int c = lane & 3, g = lane >> 2;
#pragma unroll
    for (int ks = 0; ks < 2; ks++) {
        int kp = ks*8 + c;
        uint32_t ah[2][4], al[2][4];
#pragma unroll
        for (int am = 0; am < 2; am++) {
            int R = warpM*32 + am*16 + g;
            ah[am][0] = sm.Ahi[kp][R];   ah[am][1] = sm.Ahi[kp][R+8];
            ah[am][2] = sm.Ahi[kp+4][R]; ah[am][3] = sm.Ahi[kp+4][R+8];
            al[am][0] = sm.Alo[kp][R];   al[am][1] = sm.Alo[kp][R+8];
            al[am][2] = sm.Alo[kp+4][R]; al[am][3] = sm.Alo[kp+4][R+8];
        }
#pragma unroll
        for (int bn = 0; bn < 8; bn++) {
            int nc = warpN*64 + bn*8 + g;
            uint32_t bh0 = sm.Bhi[kp][nc], bh1 = sm.Bhi[kp+4][nc];
            uint32_t bl0 = sm.Blo[kp][nc], bl1 = sm.Blo[kp+4][nc];
#pragma unroll
            for (int am = 0; am < 2; am++) {
                mma_bf16(acc[am][bn], ah[am][0],ah[am][1],ah[am][2],ah[am][3], bh0, bh1);
                mma_bf16(acc[am][bn], ah[am][0],ah[am][1],ah[am][2],ah[am][3], bl0, bl1);
                mma_bf16(acc[am][bn], al[am][0],al[am][1],al[am][2],al[am][3], bh0, bh1);
            }
        }
    }
}

// A fill: thread owns (row arow, k-half akq): 16 consecutive floats -> 8 packed pairs
__device__ __forceinline__ void sts_A(SmemT& sm, const float4 aR[4], int arow, int akq) {
    const float* f = (const float*)aR;
#pragma unroll
    for (int j = 0; j < 8; j++) {
        uint32_t hi, lo;
        split_pair(f[2*j], f[2*j+1], hi, lo);
        sm.Ahi[akq*8+j][arow] = hi;
        sm.Alo[akq*8+j][arow] = lo;
    }
}

// A fill (pre-packed source, gemm2): 8 hi words + 8 lo words
__device__ __forceinline__ void sts_A_packed(SmemT& sm, const uint4 ahR[2], const uint4 alR[2],
                                             int arow, int akq) {
    const uint32_t* h = (const uint32_t*)ahR;
    const uint32_t* l = (const uint32_t*)alR;
#pragma unroll
    for (int j = 0; j < 8; j++) {
        sm.Ahi[akq*8+j][arow] = h[j];
        sm.Alo[akq*8+j][arow] = l[j];
    }
}

// B fill: thread owns k-pair bkp, n block bn8..bn8+7; bR[0..1]=row 2kp, bR[2..3]=row 2kp+1
__device__ __forceinline__ void sts_B(SmemT& sm, const float4 bR[4], int bkp, int bn8) {
    const float* ev = (const float*)&bR[0];
    const float* od = (const float*)&bR[2];
    uint32_t hb[8], lb[8];
#pragma unroll
    for (int j = 0; j < 8; j++) split_pair(ev[j], od[j], hb[j], lb[j]);
    *(uint4*)&sm.Bhi[bkp][bn8]   = *(const uint4*)&hb[0];
    *(uint4*)&sm.Bhi[bkp][bn8+4] = *(const uint4*)&hb[4];
    *(uint4*)&sm.Blo[bkp][bn8]   = *(const uint4*)&lb[0];
    *(uint4*)&sm.Blo[bkp][bn8+4] = *(const uint4*)&lb[4];
}

// ---------------- GEMM0: rf = ln_ctx @ ctx_W + base ----------------
__global__ __launch_bounds__(256)
void k_gemm0(const float* __restrict__ ctxW)
{
    __shared__ SmemT sm;
    int tid = threadIdx.x, lane = tid & 31, wid = tid >> 5;
    int warpM = wid >> 1, warpN = wid & 1;
    int m0 = blockIdx.y * BM, n0 = blockIdx.x * BN;
    float acc[2][8][4] = {};
    int arow = tid >> 1, akq = tid & 1;
    int bkp = tid >> 4, bn8 = (tid & 15) * 8;
    const float* Aptr = g_ln_ctx + (size_t)(m0 + arow) * Dd + akq*16;
    const float* Bptr = ctxW + n0 + bn8;
    float4 aR[4], bR[4];
    // prologue
#pragma unroll
    for (int q = 0; q < 4; q++) aR[q] = ((const float4*)Aptr)[q];
    {
        const float* r0 = Bptr + (size_t)(2*bkp) * Dd;
        bR[0] = ((const float4*)r0)[0]; bR[1] = ((const float4*)r0)[1];
        bR[2] = ((const float4*)(r0+Dd))[0]; bR[3] = ((const float4*)(r0+Dd))[1];
    }
    const int NT = Dd / BKK;
    for (int t = 0; t < NT; t++) {
        sts_A(sm, aR, arow, akq);
        sts_B(sm, bR, bkp, bn8);
        __syncthreads();
        if (t + 1 < NT) {
            int k0 = (t+1) * BKK;
#pragma unroll
            for (int q = 0; q < 4; q++) aR[q] = ((const float4*)(Aptr + k0))[q];
            const float* r0 = Bptr + (size_t)(k0 + 2*bkp) * Dd;
            bR[0] = ((const float4*)r0)[0]; bR[1] = ((const float4*)r0)[1];
            bR[2] = ((const float4*)(r0+Dd))[0]; bR[3] = ((const float4*)(r0+Dd))[1];
        }
        tile_compute(sm, acc, lane, warpM, warpN);
        __syncthreads();
    }
#pragma unroll
    for (int am = 0; am < 2; am++) {
#pragma unroll
        for (int bn = 0; bn < 8; bn++) {
            int col = n0 + warpN*64 + bn*8 + (lane & 3)*2;
            int r0 = m0 + warpM*32 + am*16 + (lane >> 2);
            size_t o0 = (size_t)r0 * Dd + col;
            size_t o1 = (size_t)(r0 + 8) * Dd + col;
            g_rf[o0]   = acc[am][bn][0] + g_base[o0];
            g_rf[o0+1] = acc[am][bn][1] + g_base[o0+1];
            g_rf[o1]   = acc[am][bn][2] + g_base[o1];
            g_rf[o1+1] = acc[am][bn][3] + g_base[o1+1];
        }
    }
}

// ---------------- Router ----------------
__global__ void k_router(const float* __restrict__ rtrW, const float* __restrict__ rtrb,
                         const float* __restrict__ temp)
{
    __shared__ float sprob[8][8];
    __shared__ float slse2[8];
    __shared__ float sent[8];
    int warp = threadIdx.x >> 5, lane = threadIdx.x & 31;
    int t = blockIdx.x * 8 + warp;
    const float* rf = g_rf + (size_t)t * Dd;
    float lg[8] = {};
#pragma unroll
    for (int i = 0; i < 16; i++) {
        int d = i*32 + lane;
        float v = rf[d];
        const float4* w = (const float4*)(rtrW + (size_t)d * Ee);
        float4 w0 = w[0], w1 = w[1];
        lg[0] += v*w0.x; lg[1] += v*w0.y; lg[2] += v*w0.z; lg[3] += v*w0.w;
        lg[4] += v*w1.x; lg[5] += v*w1.y; lg[6] += v*w1.z; lg[7] += v*w1.w;
    }
#pragma unroll
    for (int o = 16; o > 0; o >>= 1)
#pragma unroll
        for (int e = 0; e < 8; e++)
            lg[e] += __shfl_xor_sync(~0u, lg[e], o);
    if (lane == 0) {
        float invT = 1.f / fmaxf(temp[0], 0.25f);
        float l[8];
#pragma unroll
        for (int e = 0; e < 8; e++) l[e] = (lg[e] + rtrb[e]) * invT;
        float mx = l[0];
#pragma unroll
        for (int e = 1; e < 8; e++) mx = fmaxf(mx, l[e]);
        float ex[8], se = 0.f;
#pragma unroll
        for (int e = 0; e < 8; e++) { ex[e] = expf(l[e] - mx); se += ex[e]; }
        float lse = logf(se) + mx;
        float inv_se = 1.f / se;
        float ent = 0.f;
#pragma unroll
        for (int e = 0; e < 8; e++) {
            float p = ex[e] * inv_se;
            ent -= p * logf(fmaxf(p, 1e-9f));
            sprob[warp][e] = p;
        }
        slse2[warp] = lse * lse;
        sent[warp] = ent;
        int i0 = 0;
#pragma unroll
        for (int e = 1; e < 8; e++) if (l[e] > l[i0]) i0 = e;
        int i1 = (i0 == 0) ? 1 : 0;
#pragma unroll
        for (int e = 0; e < 8; e++) { if (e == i0 || e == i1) continue; if (l[e] > l[i1]) i1 = e; }
        float d1 = expf(l[i1] - l[i0]);
        float g0 = 1.f / (1.f + d1);
        float g1 = d1 * g0;
        int p0 = t*2, p1 = t*2 + 1;
        g_gate[p0] = g0; g_gate[p1] = g1;
        int s0 = atomicAdd(&g_ecount[i0], 1);
        g_elist[i0*NTOK + s0] = p0;
        int s1 = atomicAdd(&g_ecount[i1], 1);
        g_elist[i1*NTOK + s1] = p1;
    }
    __syncthreads();
    int tid = threadIdx.x;
    if (tid < 8) {
        float s = 0.f;
#pragma unroll
        for (int w = 0; w < 8; w++) s += sprob[w][tid];
        atomicAdd(&g_aux[tid], s);
    } else if (tid == 8) {
        float s = 0.f;
#pragma unroll
        for (int w = 0; w < 8; w++) s += slse2[w];
        atomicAdd(&g_aux[8], s);
    } else if (tid == 9) {
        float s = 0.f;
#pragma unroll
        for (int w = 0; w < 8; w++) s += sent[w];
        atomicAdd(&g_aux[9], s);
    }
}

// ---------------- GEMM1 (grouped gather): h = gelu(x[tok] @ W1[e] + b1[e]), packed output ----------------
__global__ __launch_bounds__(256)
void k_gemm1(const float* __restrict__ x, const float* __restrict__ W1,
             const float* __restrict__ b1)
{
    __shared__ SmemT sm;
    __shared__ int sPair[BM];
    __shared__ int sTokOff[BM];
    int e = blockIdx.z;
    int cnt = g_ecount[e];
    int m0 = blockIdx.y * BM;
    if (m0 >= cnt) return;
    int n0 = blockIdx.x * BN;
    int tid = threadIdx.x, lane = tid & 31, wid = tid >> 5;
    int warpM = wid >> 1, warpN = wid & 1;
    float acc[2][8][4] = {};
    if (tid < BM) {
        int gm = m0 + tid;
        int p = g_elist[e*NTOK + (gm < cnt ? gm : 0)];
        sPair[tid] = p;
        sTokOff[tid] = (p >> 1) * Dd;
    }
    __syncthreads();
    int arow = tid >> 1, akq = tid & 1;
    int bkp = tid >> 4, bn8 = (tid & 15) * 8;
    const float* Aptr = x + sTokOff[arow] + akq*16;
    const float* Bptr = W1 + (size_t)e * Dd * Hh + n0 + bn8;
    float4 aR[4], bR[4];
#pragma unroll
    for (int q = 0; q < 4; q++) aR[q] = ((const float4*)Aptr)[q];
    {
        const float* r0 = Bptr + (size_t)(2*bkp) * Hh;
        bR[0] = ((const float4*)r0)[0]; bR[1] = ((const float4*)r0)[1];
        bR[2] = ((const float4*)(r0+Hh))[0]; bR[3] = ((const float4*)(r0+Hh))[1];
    }
    const int NT = Dd / BKK;
    for (int t = 0; t < NT; t++) {
        sts_A(sm, aR, arow, akq);
        sts_B(sm, bR, bkp, bn8);
        __syncthreads();
        if (t + 1 < NT) {
            int k0 = (t+1) * BKK;
#pragma unroll
            for (int q = 0; q < 4; q++) aR[q] = ((const float4*)(Aptr + k0))[q];
            const float* r0 = Bptr + (size_t)(k0 + 2*bkp) * Hh;
            bR[0] = ((const float4*)r0)[0]; bR[1] = ((const float4*)r0)[1];
            bR[2] = ((const float4*)(r0+Hh))[0]; bR[3] = ((const float4*)(r0+Hh))[1];
        }
        tile_compute(sm, acc, lane, warpM, warpN);
        __syncthreads();
    }
#pragma unroll
    for (int am = 0; am < 2; am++) {
#pragma unroll
        for (int bn = 0; bn < 8; bn++) {
            int col = n0 + warpN*64 + bn*8 + (lane & 3)*2;
            int mr0 = warpM*32 + am*16 + (lane >> 2);
#pragma unroll
            for (int half = 0; half < 2; half++) {
                int m = mr0 + half*8;
                if (m0 + m < cnt) {
                    int p = sPair[m];
                    const float* br = b1 + (size_t)e * Hh;
                    float v0 = acc[am][bn][half*2]   + br[col];
                    float v1 = acc[am][bn][half*2+1] + br[col+1];
                    float gv0 = 0.5f * v0 * (1.f + erff(v0 * 0.70710678118f));
                    float gv1 = 0.5f * v1 * (1.f + erff(v1 * 0.70710678118f));
                    uint32_t hw, lw;
                    split_pair(gv0, gv1, hw, lw);
                    size_t o = (size_t)p * (Hh/2) + (col >> 1);
                    g_hhi[o] = hw;
                    g_hlo[o] = lw;
                }
            }
        }
    }
}

// ---------------- GEMM2 (grouped): y = gate * (h @ W2[e] + b2[e]) ----------------
__global__ __launch_bounds__(256)
void k_gemm2(const float* __restrict__ W2, const float* __restrict__ b2)
{
    __shared__ SmemT sm;
    __shared__ int sPair[BM];
    int e = blockIdx.z;
    int cnt = g_ecount[e];
    int m0 = blockIdx.y * BM;
    if (m0 >= cnt) return;
    int n0 = blockIdx.x * BN;
    int tid = threadIdx.x, lane = tid & 31, wid = tid >> 5;
    int warpM = wid >> 1, warpN = wid & 1;
    float acc[2][8][4] = {};
    if (tid < BM) {
        int gm = m0 + tid;
        sPair[tid] = g_elist[e*NTOK + (gm < cnt ? gm : 0)];
    }
    __syncthreads();
    int arow = tid >> 1, akq = tid & 1;
    int bkp = tid >> 4, bn8 = (tid & 15) * 8;
    size_t awoff = (size_t)sPair[arow] * (Hh/2) + akq*8;
    const float* Bptr = W2 + (size_t)e * Hh * Dd + n0 + bn8;
    uint4 ahR[2], alR[2];
    float4 bR[4];
    ahR[0] = ((const uint4*)(g_hhi + awoff))[0];
    ahR[1] = ((const uint4*)(g_hhi + awoff))[1];
    alR[0] = ((const uint4*)(g_hlo + awoff))[0];
    alR[1] = ((const uint4*)(g_hlo + awoff))[1];
    {
        const float* r0 = Bptr + (size_t)(2*bkp) * Dd;
        bR[0] = ((const float4*)r0)[0]; bR[1] = ((const float4*)r0)[1];
        bR[2] = ((const float4*)(r0+Dd))[0]; bR[3] = ((const float4*)(r0+Dd))[1];
    }
    const int NT = Hh / BKK;
    for (int t = 0; t < NT; t++) {
        sts_A_packed(sm, ahR, alR, arow, akq);
        sts_B(sm, bR, bkp, bn8);
        __syncthreads();
        if (t + 1 < NT) {
            int k0 = (t+1) * BKK;
            size_t aw = awoff + k0/2;
            ahR[0] = ((const uint4*)(g_hhi + aw))[0];
            ahR[1] = ((const uint4*)(g_hhi + aw))[1];
            alR[0] = ((const uint4*)(g_hlo + aw))[0];
            alR[1] = ((const uint4*)(g_hlo + aw))[1];
            const float* r0 = Bptr + (size_t)(k0 + 2*bkp) * Dd;
            bR[0] = ((const float4*)r0)[0]; bR[1] = ((const float4*)r0)[1];
            bR[2] = ((const float4*)(r0+Dd))[0]; bR[3] = ((const float4*)(r0+Dd))[1];
        }
        tile_compute(sm, acc, lane, warpM, warpN);
        __syncthreads();
    }
#pragma unroll
    for (int am = 0; am < 2; am++) {
#pragma unroll
        for (int bn = 0; bn < 8; bn++) {
            int col = n0 + warpN*64 + bn*8 + (lane & 3)*2;
            int mr0 = warpM*32 + am*16 + (lane >> 2);
#pragma unroll
            for (int half = 0; half < 2; half++) {
                int m = mr0 + half*8;
                if (m0 + m < cnt) {
                    int p = sPair[m];
                    float gate = g_gate[p];
                    float* orow = g_y + (size_t)p * Dd;
                    const float* br = b2 + (size_t)e * Dd;
                    orow[col]   = gate * (acc[am][bn][half*2]   + br[col]);
                    orow[col+1] = gate * (acc[am][bn][half*2+1] + br[col+1]);
                }
            }
        }
    }
}

// ---------------- combine ----------------
__global__ void k_combine(float* __restrict__ out)
{
    int i = blockIdx.x * 256 + threadIdx.x;
    int t = i >> 9;
    int d = i & 511;
    size_t base = (size_t)t * (2*Dd) + d;
    out[i] = g_y[base] + g_y[base + Dd];
}

// ---------------- finalize ----------------
__global__ void k_finalize(float* __restrict__ out)
{
    if (threadIdx.x == 0) {
        const float inv = 1.f / (float)NTOK;
        float lb = 0.f;
#pragma unroll
        for (int e = 0; e < Ee; e++) {
            float d = g_aux[e] * inv - 1.f / (float)Ee;
            lb += d * d;
        }
        lb *= 1.f / (float)Ee;
        float rz = g_aux[8] * inv;
        float ent = g_aux[9] * inv;
        out[NTOK*Dd + 0] = lb;
        out[NTOK*Dd + 1] = rz;
        out[NTOK*Dd + 2] = ent;
        out[NTOK*Dd + 3] = lb + 0.001f * rz - 0.001f * ent;
    }
}

// ---------------- launch ----------------
extern "C" void kernel_launch(void* const* d_in, const int* in_sizes, int n_in,
                              void* d_out, int out_size)
{
    const float* x       = (const float*)d_in[0];
    const float* ctx     = (const float*)d_in[1];
    const float* quality = (const float*)d_in[2];
    const float* rn_g    = (const float*)d_in[3];
    const float* rn_b    = (const float*)d_in[4];
    const float* cn_g    = (const float*)d_in[5];
    const float* cn_b    = (const float*)d_in[6];
    const float* ctx_W   = (const float*)d_in[7];
    const float* ctx_b   = (const float*)d_in[8];
    const float* qual_W  = (const float*)d_in[9];
    const float* qual_b  = (const float*)d_in[10];
    const float* rtr_W   = (const float*)d_in[11];
    const float* rtr_b   = (const float*)d_in[12];
    const float* temp    = (const float*)d_in[13];
    const float* W1      = (const float*)d_in[14];
    const float* b1      = (const float*)d_in[15];
    const float* W2      = (const float*)d_in[16];
    const float* b2      = (const float*)d_in[17];
    float* out = (float*)d_out;

    k_init<<<1, 32>>>();
    k_ln<<<NTOK/8, 256>>>(x, ctx, quality, rn_g, rn_b, cn_g, cn_b, ctx_b, qual_W, qual_b);
    k_gemm0<<<dim3(Dd/BN, NTOK/BM), 256>>>(ctx_W);
    k_router<<<NTOK/8, 256>>>(rtr_W, rtr_b, temp);
    k_gemm1<<<dim3(Hh/BN, NTOK/BM, Ee), 256>>>(x, W1, b1);
    k_gemm2<<<dim3(Dd/BN, NTOK/BM, Ee), 256>>>(W2, b2);
    k_combine<<<(NTOK*Dd)/256, 256>>>(out);
    k_finalize<<<1, 32>>>(out);
}